// round 2
// baseline (speedup 1.0000x reference)
#include <cuda_runtime.h>

#define DIN 448
#define HEADS 8
#define HD 56
#define BATCH 8
#define SEQ 8192
#define TOKENS (BATCH*SEQ)   // 65536

// Scratch (device globals; no allocation allowed in kernel_launch)
__device__ float E_g[DIN * DIN];                 // collapsed per-head operator, row-major [o, i]
__device__ float Yg[(size_t)TOKENS * DIN];      // pre-LN GEMM1 output (plain token order)
__device__ float Yn[(size_t)TOKENS * DIN];      // permuted + normalized rows

// ---------------------------------------------------------------------------
// Kernel 0: E_h = C_h * M^T * A_h^T * B_h   (tiny, 8 blocks x 448 threads)
// ---------------------------------------------------------------------------
__global__ void computeE(const float* __restrict__ A,
                         const float* __restrict__ B,
                         const float* __restrict__ C) {
    __shared__ float As[HD * HD];
    __shared__ float Cs[HD * HD];
    const int h = blockIdx.x;
    const int tid = threadIdx.x;           // 448 threads, one output column each
    for (int i = tid; i < HD * HD; i += blockDim.x) {
        As[i] = A[h * HD * HD + i];
        Cs[i] = C[h * HD * HD + i];
    }
    __syncthreads();

    const int i = tid;                      // column index in [0,448)
    float t1[HD];
    #pragma unroll
    for (int e = 0; e < HD; e++) t1[e] = 0.f;

    // T1[e,i] = sum_d A[h,d,e] * B[h,d,i]
    for (int d = 0; d < HD; d++) {
        float bb = B[(size_t)(h * HD + d) * DIN + i];
        #pragma unroll
        for (int e = 0; e < HD; e++) t1[e] += As[d * HD + e] * bb;
    }
    // T2 = M^T T1 : suffix sum over e
    #pragma unroll
    for (int e = HD - 2; e >= 0; e--) t1[e] += t1[e + 1];
    // E[h*56+o, i] = sum_e C[h,o,e] * T2[e,i]
    for (int o = 0; o < HD; o++) {
        float s = 0.f;
        #pragma unroll
        for (int e = 0; e < HD; e++) s += Cs[o * HD + e] * t1[e];
        E_g[(size_t)(h * HD + o) * DIN + i] = s;
    }
}

// ---------------------------------------------------------------------------
// GEMM: C[M,N] = A[M,K] * B[N,K]^T  via mma.sync tf32 (m16n8k8)
// M=65536, N=448, K=448.  Block tile 128x64, BK=32, 8 warps (4x2),
// warp tile 32x32 (2 m-tiles x 4 n-tiles). XOR-swizzled smem, 2-stage pipe.
// ---------------------------------------------------------------------------
#define BM 128
#define BN 64
#define BK 32

__device__ __forceinline__ unsigned f2tf(float f) {
    unsigned u;
    asm("cvt.rna.tf32.f32 %0, %1;" : "=r"(u) : "f"(f));
    return u;
}

__global__ __launch_bounds__(256) void gemm_tf32(
    const float* __restrict__ Ag,   // [M, 448]
    const float* __restrict__ Bg,   // [448, 448] row-major [n, k]
    float* __restrict__ Cg,         // [M, 448]
    const float* __restrict__ bias) // nullable
{
    __shared__ float Xs[2][BM * BK];   // 32 KB
    __shared__ float Ws[2][BN * BK];   // 16 KB  (total 48 KB)

    const int tid  = threadIdx.x;
    const int warp = tid >> 5, lane = tid & 31;
    const int wm = warp & 3, wn = warp >> 2;          // 4 (M) x 2 (N)
    const int M0 = blockIdx.y * BM;                   // grid: (7 N-blocks, 512 M-blocks)
    const int N0 = blockIdx.x * BN;
    const int lg = lane >> 2;    // group id (0..7)
    const int li = lane & 3;     // id in group (0..3)

    float acc[2][4][4];
    #pragma unroll
    for (int mt = 0; mt < 2; mt++)
        #pragma unroll
        for (int nt = 0; nt < 4; nt++)
            #pragma unroll
            for (int r = 0; r < 4; r++) acc[mt][nt][r] = 0.f;

    const int NT = DIN / BK;  // 14
    float4 xa[4], wa[2];

    // ---- prologue: load tile 0 into smem buffer 0 ----
    #pragma unroll
    for (int j = 0; j < 4; j++) {
        int idx = tid + j * 256, r = idx >> 3, c4 = idx & 7;
        xa[j] = *(const float4*)&Ag[(size_t)(M0 + r) * DIN + c4 * 4];
    }
    #pragma unroll
    for (int j = 0; j < 2; j++) {
        int idx = tid + j * 256, r = idx >> 3, c4 = idx & 7;
        wa[j] = *(const float4*)&Bg[(size_t)(N0 + r) * DIN + c4 * 4];
    }
    #pragma unroll
    for (int j = 0; j < 4; j++) {
        int idx = tid + j * 256, r = idx >> 3, c4 = idx & 7;
        *(float4*)&Xs[0][r * BK + ((c4 ^ (r & 7)) << 2)] = xa[j];
    }
    #pragma unroll
    for (int j = 0; j < 2; j++) {
        int idx = tid + j * 256, r = idx >> 3, c4 = idx & 7;
        *(float4*)&Ws[0][r * BK + ((c4 ^ (r & 7)) << 2)] = wa[j];
    }

    for (int kt = 0; kt < NT; kt++) {
        __syncthreads();
        const int cb = kt & 1, nb = cb ^ 1;
        const bool more = (kt + 1 < NT);

        if (more) {   // prefetch next K-tile (global -> regs), overlaps compute
            const int kofs = (kt + 1) * BK;
            #pragma unroll
            for (int j = 0; j < 4; j++) {
                int idx = tid + j * 256, r = idx >> 3, c4 = idx & 7;
                xa[j] = *(const float4*)&Ag[(size_t)(M0 + r) * DIN + kofs + c4 * 4];
            }
            #pragma unroll
            for (int j = 0; j < 2; j++) {
                int idx = tid + j * 256, r = idx >> 3, c4 = idx & 7;
                wa[j] = *(const float4*)&Bg[(size_t)(N0 + r) * DIN + kofs + c4 * 4];
            }
        }

        #pragma unroll
        for (int kk = 0; kk < 4; kk++) {
            const int g0 = 2 * kk, g1 = 2 * kk + 1;
            unsigned af[2][4], bf[4][2];
            #pragma unroll
            for (int mt = 0; mt < 2; mt++) {
                int r0 = wm * 32 + mt * 16 + lg;
                int sw0 = (g0 ^ (r0 & 7)) << 2, sw1 = (g1 ^ (r0 & 7)) << 2;
                af[mt][0] = f2tf(Xs[cb][r0 * BK + sw0 + li]);
                af[mt][1] = f2tf(Xs[cb][(r0 + 8) * BK + sw0 + li]);
                af[mt][2] = f2tf(Xs[cb][r0 * BK + sw1 + li]);
                af[mt][3] = f2tf(Xs[cb][(r0 + 8) * BK + sw1 + li]);
            }
            #pragma unroll
            for (int nt = 0; nt < 4; nt++) {
                int n0 = wn * 32 + nt * 8 + lg;
                bf[nt][0] = f2tf(Ws[cb][n0 * BK + ((g0 ^ (n0 & 7)) << 2) + li]);
                bf[nt][1] = f2tf(Ws[cb][n0 * BK + ((g1 ^ (n0 & 7)) << 2) + li]);
            }
            #pragma unroll
            for (int mt = 0; mt < 2; mt++)
                #pragma unroll
                for (int nt = 0; nt < 4; nt++) {
                    asm volatile(
                        "mma.sync.aligned.m16n8k8.row.col.f32.tf32.tf32.f32 "
                        "{%0,%1,%2,%3}, {%4,%5,%6,%7}, {%8,%9}, {%0,%1,%2,%3};\n"
                        : "+f"(acc[mt][nt][0]), "+f"(acc[mt][nt][1]),
                          "+f"(acc[mt][nt][2]), "+f"(acc[mt][nt][3])
                        : "r"(af[mt][0]), "r"(af[mt][1]), "r"(af[mt][2]), "r"(af[mt][3]),
                          "r"(bf[nt][0]), "r"(bf[nt][1]));
                }
        }

        if (more) {   // stash prefetched tile into the other buffer
            #pragma unroll
            for (int j = 0; j < 4; j++) {
                int idx = tid + j * 256, r = idx >> 3, c4 = idx & 7;
                *(float4*)&Xs[nb][r * BK + ((c4 ^ (r & 7)) << 2)] = xa[j];
            }
            #pragma unroll
            for (int j = 0; j < 2; j++) {
                int idx = tid + j * 256, r = idx >> 3, c4 = idx & 7;
                *(float4*)&Ws[nb][r * BK + ((c4 ^ (r & 7)) << 2)] = wa[j];
            }
        }
    }

    // ---- epilogue ----
    #pragma unroll
    for (int mt = 0; mt < 2; mt++) {
        int r0 = M0 + wm * 32 + mt * 16 + lg;
        #pragma unroll
        for (int nt = 0; nt < 4; nt++) {
            int c0 = N0 + wn * 32 + nt * 8 + li * 2;
            float b0 = 0.f, b1 = 0.f;
            if (bias) { b0 = bias[c0]; b1 = bias[c0 + 1]; }
            float2 v0 = make_float2(acc[mt][nt][0] + b0, acc[mt][nt][1] + b1);
            float2 v1 = make_float2(acc[mt][nt][2] + b0, acc[mt][nt][3] + b1);
            *(float2*)&Cg[(size_t)r0 * DIN + c0]       = v0;
            *(float2*)&Cg[(size_t)(r0 + 8) * DIN + c0] = v1;
        }
    }
}

// ---------------------------------------------------------------------------
// LN + reshape-permutation: out row R = b*8192 + h*1024 + q gathers
// Yg[b*8192 + 8q + r, h*56 + d] at channel c = r*56 + d, then LayerNorm.
// One warp per row. 448 = 14 * 32.
// ---------------------------------------------------------------------------
__global__ void ln_permute(const float* __restrict__ Y, float* __restrict__ Out,
                           const float* __restrict__ gamma,
                           const float* __restrict__ beta) {
    const int warp = threadIdx.x >> 5, lane = threadIdx.x & 31;
    const int R = blockIdx.x * 8 + warp;     // [0, 65536)
    const int b   = R >> 13;
    const int rem = R & 8191;
    const int h   = rem >> 10;
    const int q   = rem & 1023;

    float v[14];
    #pragma unroll
    for (int j = 0; j < 14; j++) {
        int c = lane + 32 * j;
        int r = c / 56, d = c - r * 56;
        v[j] = Y[(size_t)(b * SEQ + 8 * q + r) * DIN + h * HD + d];
    }
    float s = 0.f;
    #pragma unroll
    for (int j = 0; j < 14; j++) s += v[j];
    #pragma unroll
    for (int o = 16; o > 0; o >>= 1) s += __shfl_xor_sync(0xffffffffu, s, o);
    const float mu = s * (1.f / 448.f);

    float vs = 0.f;
    #pragma unroll
    for (int j = 0; j < 14; j++) { float d2 = v[j] - mu; vs += d2 * d2; }
    #pragma unroll
    for (int o = 16; o > 0; o >>= 1) vs += __shfl_xor_sync(0xffffffffu, vs, o);
    const float rsig = rsqrtf(vs * (1.f / 448.f) + 1e-5f);

    #pragma unroll
    for (int j = 0; j < 14; j++) {
        int c = lane + 32 * j;
        Out[(size_t)R * DIN + c] = (v[j] - mu) * rsig * gamma[c] + beta[c];
    }
}

// ---------------------------------------------------------------------------
extern "C" void kernel_launch(void* const* d_in, const int* in_sizes, int n_in,
                              void* d_out, int out_size) {
    const float* x     = (const float*)d_in[0];
    const float* A     = (const float*)d_in[1];
    const float* B     = (const float*)d_in[2];
    const float* C     = (const float*)d_in[3];
    const float* gamma = (const float*)d_in[4];
    const float* beta  = (const float*)d_in[5];
    const float* W     = (const float*)d_in[6];
    const float* bias  = (const float*)d_in[7];
    float* out = (float*)d_out;

    float *E_p, *Yg_p, *Yn_p;
    cudaGetSymbolAddress((void**)&E_p,  E_g);
    cudaGetSymbolAddress((void**)&Yg_p, Yg);
    cudaGetSymbolAddress((void**)&Yn_p, Yn);

    computeE<<<HEADS, DIN>>>(A, B, C);

    dim3 grid(DIN / BN, TOKENS / BM);   // (7, 512): N fastest for L2 reuse of X tiles
    gemm_tf32<<<grid, 256>>>(x, E_p, Yg_p, nullptr);

    ln_permute<<<TOKENS / 8, 256>>>(Yg_p, Yn_p, gamma, beta);

    gemm_tf32<<<grid, 256>>>(Yn_p, W, out, bias);
}

// round 4
// speedup vs baseline: 1.1205x; 1.1205x over previous
#include <cuda_runtime.h>
#include <cstdint>

#define DIN 448
#define HEADS 8
#define HD 56
#define SEQ 8192
#define TOKENS 65536

// ---------------- scratch (device globals; no runtime alloc) ---------------
__device__ float E_g[DIN * DIN];
__device__ float Wc_g[DIN * DIN];
__device__ float Xc_g[(size_t)TOKENS * DIN];
__device__ float Yg_g[(size_t)TOKENS * DIN];
__device__ float Yn_g[(size_t)TOKENS * DIN];

// ---------------- helpers --------------------------------------------------
__device__ __forceinline__ uint32_t smem_u32(const void* p) {
    uint32_t a;
    asm("{ .reg .u64 t; cvta.to.shared.u64 t, %1; cvt.u32.u64 %0, t; }"
        : "=r"(a) : "l"(p));
    return a;
}
__device__ __forceinline__ float tf32r(float f) {   // round-to-nearest tf32
    uint32_t u;
    asm("cvt.rna.tf32.f32 %0, %1;" : "=r"(u) : "f"(f));
    return __uint_as_float(u);
}
#define CP_ASYNC16(dst, src) \
    asm volatile("cp.async.cg.shared.global [%0], [%1], 16;" :: "r"(dst), "l"(src) : "memory")
#define CP_COMMIT() asm volatile("cp.async.commit_group;" ::: "memory")
#define CP_WAIT(n)  asm volatile("cp.async.wait_group %0;" :: "n"(n) : "memory")

// ---------------- GEMM: C[M,448] = A[M,448] * B[448,448]^T -----------------
// Block 256x64, BK=32, 8 warps (4m x 2n), warp tile 64x32 (4 m16 x 4 n8).
// Inputs pre-rounded to tf32. SW128-swizzled smem, LDS.64 fragment pairs via
// k-relabel (hw k=li -> phys 2li, hw k=li+4 -> phys 2li+1), 3-stage cp.async.
#define GBM 256
#define GBN 64
#define GBK 32
#define NSTAGE 3
#define A_BYTES (GBM * 128)                 // 32768 per stage
#define B_BYTES (GBN * 128)                 // 8192 per stage
#define SB_OFF  (NSTAGE * A_BYTES)          // 98304
#define GSMEM   (SB_OFF + NSTAGE * B_BYTES) // 122880

__global__ __launch_bounds__(256) void gemm_tf32(
    const float* __restrict__ Ag,   // [M, 448] tf32-rounded
    const float* __restrict__ Bg,   // [448, 448] row-major [n,k], tf32-rounded
    float* __restrict__ Cg,         // [M, 448]
    const float* __restrict__ bias) // nullable
{
    extern __shared__ char sm[];
    const uint32_t sb = smem_u32(sm);
    const int tid  = threadIdx.x;
    const int warp = tid >> 5, lane = tid & 31;
    const int wm = warp >> 1, wn = warp & 1;
    const int g  = lane >> 2, li = lane & 3;
    const size_t M0 = (size_t)blockIdx.y * GBM;
    const int    N0 = blockIdx.x * GBN;

    float acc[4][4][4];
    #pragma unroll
    for (int mt = 0; mt < 4; mt++)
        #pragma unroll
        for (int nt = 0; nt < 4; nt++)
            #pragma unroll
            for (int r = 0; r < 4; r++) acc[mt][nt][r] = 0.f;

    // per-thread copy descriptors
    const int cr = tid >> 3, cc = tid & 7;          // A: rows cr+32j ; B: rows cr+32j (j<2)
    const uint32_t csw = (uint32_t)((cc ^ (cr & 7)) << 4);

    // fragment row offsets (row&7 == g for all tiles)
    uint32_t arow[4], brow[4];
    #pragma unroll
    for (int mt = 0; mt < 4; mt++) arow[mt] = (uint32_t)((wm * 64 + mt * 16 + g) * 128);
    #pragma unroll
    for (int nt = 0; nt < 4; nt++) brow[nt] = (uint32_t)((wn * 32 + nt * 8 + g) * 128);

    const int NT = DIN / GBK;   // 14

    // tile loader: stage st <- K-tile kt
    auto load_tile = [&](int kt, int st) {
        const float* asrc = Ag + M0 * DIN + (size_t)kt * GBK;
        const uint32_t ab = sb + st * A_BYTES;
        #pragma unroll
        for (int j = 0; j < 8; j++) {
            int r = cr + 32 * j;
            CP_ASYNC16(ab + (uint32_t)r * 128 + ((uint32_t)((cc ^ (r & 7)) << 4)),
                       asrc + (size_t)r * DIN + cc * 4);
        }
        const float* bsrc = Bg + (size_t)N0 * DIN + (size_t)kt * GBK;
        const uint32_t bb = sb + SB_OFF + st * B_BYTES;
        #pragma unroll
        for (int j = 0; j < 2; j++) {
            int r = cr + 32 * j;
            CP_ASYNC16(bb + (uint32_t)r * 128 + ((uint32_t)((cc ^ (r & 7)) << 4)),
                       bsrc + (size_t)r * DIN + cc * 4);
        }
        (void)csw;
    };

    load_tile(0, 0); CP_COMMIT();
    load_tile(1, 1); CP_COMMIT();

    for (int kt = 0; kt < NT; kt++) {
        if (kt < NT - 1) { CP_WAIT(1); } else { CP_WAIT(0); }
        __syncthreads();
        const int st = kt % NSTAGE;

        // prefetch tile kt+2 into the stage just released by tile kt-1
        if (kt + 2 < NT) { load_tile(kt + 2, (kt + 2) % NSTAGE); CP_COMMIT(); }

        const char* sa = sm + st * A_BYTES;
        const char* sbp = sm + SB_OFF + st * B_BYTES;

        #pragma unroll
        for (int kk = 0; kk < 4; kk++) {
            // swizzled in-row offset of this thread's (k=2li, 2li+1) pair
            const uint32_t sw = (uint32_t)((((2 * kk + (li >> 1)) ^ g) << 4) | ((li & 1) << 3));
            float2 a0[4], a1[4], bv[4];
            #pragma unroll
            for (int mt = 0; mt < 4; mt++) {
                a0[mt] = *(const float2*)(sa + arow[mt] + sw);          // (a0, a2)
                a1[mt] = *(const float2*)(sa + arow[mt] + 1024 + sw);   // (a1, a3)
            }
            #pragma unroll
            for (int nt = 0; nt < 4; nt++)
                bv[nt] = *(const float2*)(sbp + brow[nt] + sw);         // (b0, b1)

            #pragma unroll
            for (int mt = 0; mt < 4; mt++)
                #pragma unroll
                for (int nt = 0; nt < 4; nt++) {
                    asm volatile(
                        "mma.sync.aligned.m16n8k8.row.col.f32.tf32.tf32.f32 "
                        "{%0,%1,%2,%3}, {%4,%5,%6,%7}, {%8,%9}, {%0,%1,%2,%3};\n"
                        : "+f"(acc[mt][nt][0]), "+f"(acc[mt][nt][1]),
                          "+f"(acc[mt][nt][2]), "+f"(acc[mt][nt][3])
                        : "r"(__float_as_uint(a0[mt].x)), "r"(__float_as_uint(a1[mt].x)),
                          "r"(__float_as_uint(a0[mt].y)), "r"(__float_as_uint(a1[mt].y)),
                          "r"(__float_as_uint(bv[nt].x)), "r"(__float_as_uint(bv[nt].y)));
                }
        }
    }

    // ---- epilogue ----
    #pragma unroll
    for (int mt = 0; mt < 4; mt++) {
        const size_t r0 = M0 + wm * 64 + mt * 16 + g;
        #pragma unroll
        for (int nt = 0; nt < 4; nt++) {
            const int c0 = N0 + wn * 32 + nt * 8 + 2 * li;
            float b0 = 0.f, b1 = 0.f;
            if (bias) { b0 = bias[c0]; b1 = bias[c0 + 1]; }
            *(float2*)&Cg[r0 * DIN + c0] =
                make_float2(acc[mt][nt][0] + b0, acc[mt][nt][1] + b1);
            *(float2*)&Cg[(r0 + 8) * DIN + c0] =
                make_float2(acc[mt][nt][2] + b0, acc[mt][nt][3] + b1);
        }
    }
}

// ---------------- tf32 rounding pass ---------------------------------------
__global__ void conv_tf32(const float4* __restrict__ src, float4* __restrict__ dst, int n4) {
    int i = blockIdx.x * blockDim.x + threadIdx.x;
    if (i < n4) {
        float4 v = src[i];
        dst[i] = make_float4(tf32r(v.x), tf32r(v.y), tf32r(v.z), tf32r(v.w));
    }
}

// ---------------- E_h = C_h * M^T * A_h^T * B_h ----------------------------
// G = suffix-sum_e(A); F = C * G^T; E = F * B.  grid (8 heads, 8 o-chunks)
__global__ void computeE_k(const float* __restrict__ A, const float* __restrict__ B,
                           const float* __restrict__ C) {
    __shared__ float G[HD * HD], Cs[HD * HD], F[7 * HD];
    const int h = blockIdx.x, oc = blockIdx.y;
    const int tid = threadIdx.x;     // 448 threads
    for (int i = tid; i < HD * HD; i += 448) {
        G[i]  = A[h * HD * HD + i];
        Cs[i] = C[h * HD * HD + i];
    }
    __syncthreads();
    if (tid < HD) {
        #pragma unroll
        for (int e = HD - 2; e >= 0; e--) G[tid * HD + e] += G[tid * HD + e + 1];
    }
    __syncthreads();
    if (tid < 7 * HD) {
        int ol = tid / HD, d = tid % HD;
        float s = 0.f;
        #pragma unroll
        for (int e = 0; e < HD; e++) s += Cs[(oc * 7 + ol) * HD + e] * G[d * HD + e];
        F[ol * HD + d] = s;
    }
    __syncthreads();
    const int i = tid;
    float acc[7] = {0, 0, 0, 0, 0, 0, 0};
    for (int d = 0; d < HD; d++) {
        float b = B[(size_t)(h * HD + d) * DIN + i];
        #pragma unroll
        for (int ol = 0; ol < 7; ol++) acc[ol] += F[ol * HD + d] * b;
    }
    #pragma unroll
    for (int ol = 0; ol < 7; ol++)
        E_g[(size_t)(h * HD + oc * 7 + ol) * DIN + i] = tf32r(acc[ol]);
}

// ---------------- LayerNorm + reshape permutation (tf32-rounded out) -------
__global__ void ln_permute(const float* __restrict__ Y, float* __restrict__ Out,
                           const float* __restrict__ gamma,
                           const float* __restrict__ beta) {
    const int warp = threadIdx.x >> 5, lane = threadIdx.x & 31;
    const int R = blockIdx.x * 8 + warp;
    const int b   = R >> 13;
    const int rem = R & 8191;
    const int h   = rem >> 10;
    const int q   = rem & 1023;

    float v[14];
    #pragma unroll
    for (int j = 0; j < 14; j++) {
        int c = lane + 32 * j;
        int r = c / 56, d = c - r * 56;
        v[j] = Y[(size_t)(b * SEQ + 8 * q + r) * DIN + h * HD + d];
    }
    float s = 0.f;
    #pragma unroll
    for (int j = 0; j < 14; j++) s += v[j];
    #pragma unroll
    for (int o = 16; o > 0; o >>= 1) s += __shfl_xor_sync(0xffffffffu, s, o);
    const float mu = s * (1.f / 448.f);

    float vs = 0.f;
    #pragma unroll
    for (int j = 0; j < 14; j++) { float d2 = v[j] - mu; vs += d2 * d2; }
    #pragma unroll
    for (int o = 16; o > 0; o >>= 1) vs += __shfl_xor_sync(0xffffffffu, vs, o);
    const float rsig = rsqrtf(vs * (1.f / 448.f) + 1e-5f);

    #pragma unroll
    for (int j = 0; j < 14; j++) {
        int c = lane + 32 * j;
        Out[(size_t)R * DIN + c] = tf32r((v[j] - mu) * rsig * gamma[c] + beta[c]);
    }
}

// ---------------------------------------------------------------------------
extern "C" void kernel_launch(void* const* d_in, const int* in_sizes, int n_in,
                              void* d_out, int out_size) {
    const float* x     = (const float*)d_in[0];
    const float* A     = (const float*)d_in[1];
    const float* B     = (const float*)d_in[2];
    const float* C     = (const float*)d_in[3];
    const float* gamma = (const float*)d_in[4];
    const float* beta  = (const float*)d_in[5];
    const float* W     = (const float*)d_in[6];
    const float* bias  = (const float*)d_in[7];
    float* out = (float*)d_out;

    float *E_p, *Wc_p, *Xc_p, *Yg_p, *Yn_p;
    cudaGetSymbolAddress((void**)&E_p,  E_g);
    cudaGetSymbolAddress((void**)&Wc_p, Wc_g);
    cudaGetSymbolAddress((void**)&Xc_p, Xc_g);
    cudaGetSymbolAddress((void**)&Yg_p, Yg_g);
    cudaGetSymbolAddress((void**)&Yn_p, Yn_g);

    cudaFuncSetAttribute(gemm_tf32, cudaFuncAttributeMaxDynamicSharedMemorySize, GSMEM);

    conv_tf32<<<28672, 256>>>((const float4*)x, (float4*)Xc_p, 7340032);
    conv_tf32<<<196,   256>>>((const float4*)W, (float4*)Wc_p, 50176);
    computeE_k<<<dim3(HEADS, 8), DIN>>>(A, B, C);

    dim3 grid(DIN / GBN, TOKENS / GBM);   // (7, 256): N fastest for L2 reuse of A tiles
    gemm_tf32<<<grid, 256, GSMEM>>>(Xc_p, E_p, Yg_p, nullptr);
    ln_permute<<<TOKENS / 8, 256>>>(Yg_p, Yn_p, gamma, beta);
    gemm_tf32<<<grid, 256, GSMEM>>>(Yn_p, Wc_p, out, bias);
}

// round 5
// speedup vs baseline: 1.4594x; 1.3024x over previous
#include <cuda_runtime.h>
#include <cstdint>

#define DIN 448
#define HEADS 8
#define HD 56
#define SEQ 8192
#define TOKENS 65536

// ---------------- scratch (device globals; no runtime alloc) ---------------
__device__ float E_g[DIN * DIN];
__device__ float Wc_g[DIN * DIN];
__device__ float Xc_g[(size_t)TOKENS * DIN];
__device__ float Yg_g[(size_t)TOKENS * DIN];
__device__ float Yn_g[(size_t)TOKENS * DIN];

// ---------------- helpers --------------------------------------------------
__device__ __forceinline__ float tf32r(float f) {   // round-to-nearest tf32
    uint32_t u;
    asm("cvt.rna.tf32.f32 %0, %1;" : "=r"(u) : "f"(f));
    return __uint_as_float(u);
}
#define CP_ASYNC16(dst, src) \
    asm volatile("cp.async.cg.shared.global [%0], [%1], 16;" :: "r"(dst), "l"(src) : "memory")
#define CP_COMMIT() asm volatile("cp.async.commit_group;" ::: "memory")
#define CP_WAIT(n)  asm volatile("cp.async.wait_group %0;" :: "n"(n) : "memory")

__device__ __forceinline__ uint32_t smem_u32(const void* p) {
    uint32_t a;
    asm("{ .reg .u64 t; cvta.to.shared.u64 t, %1; cvt.u32.u64 %0, t; }"
        : "=r"(a) : "l"(p));
    return a;
}

// ---------------- GEMM: C[M,448] = A[M,448] * B[448,448]^T -----------------
// Block 256x64 with 4 warps; warp tile 64x64 (4 m16-tiles x 8 n8-tiles).
// Inputs pre-rounded to tf32. SW128-swizzled smem, LDS.64 fragment pairs via
// k-relabel (hw k=li -> phys 2li, hw k=li+4 -> phys 2li+1).
// 2-stage cp.async pipeline; 2 CTAs/SM.
#define GBM 256
#define GBN 64
#define GBK 32
#define NSTAGE 2
#define A_BYTES (GBM * 128)                 // 32768 per stage
#define B_BYTES (GBN * 128)                 // 8192 per stage
#define SB_OFF  (NSTAGE * A_BYTES)          // 65536
#define GSMEM   (SB_OFF + NSTAGE * B_BYTES) // 81920

__global__ __launch_bounds__(128, 2) void gemm_tf32(
    const float* __restrict__ Ag,   // [M, 448] tf32-rounded
    const float* __restrict__ Bg,   // [448, 448] row-major [n,k], tf32-rounded
    float* __restrict__ Cg,         // [M, 448]
    const float* __restrict__ bias) // nullable
{
    extern __shared__ char sm[];
    const uint32_t sb = smem_u32(sm);
    const int tid  = threadIdx.x;
    const int warp = tid >> 5, lane = tid & 31;
    const int g  = lane >> 2, li = lane & 3;
    const size_t M0 = (size_t)blockIdx.y * GBM;
    const int    N0 = blockIdx.x * GBN;

    float acc[4][8][4];
    #pragma unroll
    for (int mt = 0; mt < 4; mt++)
        #pragma unroll
        for (int nt = 0; nt < 8; nt++)
            #pragma unroll
            for (int r = 0; r < 4; r++) acc[mt][nt][r] = 0.f;

    // copy descriptors (128 threads)
    const int cr = tid >> 3, cc = tid & 7;        // cr in [0,16)

    // fragment row byte-offsets (row & 7 == g for every tile row base)
    uint32_t arow[4], brow[8];
    #pragma unroll
    for (int mt = 0; mt < 4; mt++) arow[mt] = (uint32_t)((warp * 64 + mt * 16 + g) * 128);
    #pragma unroll
    for (int nt = 0; nt < 8; nt++) brow[nt] = (uint32_t)((nt * 8 + g) * 128);

    const int NT = DIN / GBK;   // 14

    auto load_tile = [&](int kt, int st) {
        const float* asrc = Ag + M0 * DIN + (size_t)kt * GBK;
        const uint32_t ab = sb + st * A_BYTES;
        #pragma unroll
        for (int j = 0; j < 16; j++) {            // 256 rows x 8 chunks / 128 thr
            int r = cr + 16 * j;
            CP_ASYNC16(ab + (uint32_t)r * 128 + ((uint32_t)((cc ^ (r & 7)) << 4)),
                       asrc + (size_t)r * DIN + cc * 4);
        }
        const float* bsrc = Bg + (size_t)N0 * DIN + (size_t)kt * GBK;
        const uint32_t bb = sb + SB_OFF + st * B_BYTES;
        #pragma unroll
        for (int j = 0; j < 4; j++) {             // 64 rows x 8 chunks / 128 thr
            int r = cr + 16 * j;
            CP_ASYNC16(bb + (uint32_t)r * 128 + ((uint32_t)((cc ^ (r & 7)) << 4)),
                       bsrc + (size_t)r * DIN + cc * 4);
        }
    };

    load_tile(0, 0); CP_COMMIT();
    load_tile(1, 1); CP_COMMIT();

    for (int kt = 0; kt < NT; kt++) {
        if (kt < NT - 1) { CP_WAIT(1); } else { CP_WAIT(0); }
        __syncthreads();                          // tile kt visible to all warps
        const int st = kt & 1;
        const char* sa  = sm + st * A_BYTES;
        const char* sbp = sm + SB_OFF + st * B_BYTES;

        #pragma unroll
        for (int kk = 0; kk < 4; kk++) {
            const uint32_t sw = (uint32_t)((((2 * kk + (li >> 1)) ^ g) << 4) | ((li & 1) << 3));
            float2 a0[4], a1[4], bv[8];
            #pragma unroll
            for (int mt = 0; mt < 4; mt++) {
                a0[mt] = *(const float2*)(sa + arow[mt] + sw);          // (a0, a2)
                a1[mt] = *(const float2*)(sa + arow[mt] + 1024 + sw);   // (a1, a3)
            }
            #pragma unroll
            for (int nt = 0; nt < 8; nt++)
                bv[nt] = *(const float2*)(sbp + brow[nt] + sw);         // (b0, b1)

            #pragma unroll
            for (int mt = 0; mt < 4; mt++)
                #pragma unroll
                for (int nt = 0; nt < 8; nt++) {
                    asm volatile(
                        "mma.sync.aligned.m16n8k8.row.col.f32.tf32.tf32.f32 "
                        "{%0,%1,%2,%3}, {%4,%5,%6,%7}, {%8,%9}, {%0,%1,%2,%3};\n"
                        : "+f"(acc[mt][nt][0]), "+f"(acc[mt][nt][1]),
                          "+f"(acc[mt][nt][2]), "+f"(acc[mt][nt][3])
                        : "r"(__float_as_uint(a0[mt].x)), "r"(__float_as_uint(a1[mt].x)),
                          "r"(__float_as_uint(a0[mt].y)), "r"(__float_as_uint(a1[mt].y)),
                          "r"(__float_as_uint(bv[nt].x)), "r"(__float_as_uint(bv[nt].y)));
                }
        }

        if (kt + 2 < NT) {                        // refill the stage just consumed
            __syncthreads();                      // all warps done reading stage st
            load_tile(kt + 2, st);
            CP_COMMIT();
        }
    }

    // ---- epilogue ----
    #pragma unroll
    for (int mt = 0; mt < 4; mt++) {
        const size_t r0 = M0 + warp * 64 + mt * 16 + g;
        #pragma unroll
        for (int nt = 0; nt < 8; nt++) {
            const int c0 = N0 + nt * 8 + 2 * li;
            float b0 = 0.f, b1 = 0.f;
            if (bias) { b0 = bias[c0]; b1 = bias[c0 + 1]; }
            *(float2*)&Cg[r0 * DIN + c0] =
                make_float2(acc[mt][nt][0] + b0, acc[mt][nt][1] + b1);
            *(float2*)&Cg[(r0 + 8) * DIN + c0] =
                make_float2(acc[mt][nt][2] + b0, acc[mt][nt][3] + b1);
        }
    }
}

// ---------------- tf32 rounding pass ---------------------------------------
__global__ void conv_tf32(const float4* __restrict__ src, float4* __restrict__ dst, int n4) {
    int i = blockIdx.x * blockDim.x + threadIdx.x;
    if (i < n4) {
        float4 v = src[i];
        dst[i] = make_float4(tf32r(v.x), tf32r(v.y), tf32r(v.z), tf32r(v.w));
    }
}

// ---------------- E_h = C_h * M^T * A_h^T * B_h ----------------------------
// G = suffix-sum_e(A); F = C * G^T; E = F * B.  grid (8 heads, 8 o-chunks)
__global__ void computeE_k(const float* __restrict__ A, const float* __restrict__ B,
                           const float* __restrict__ C) {
    __shared__ float G[HD * HD], Cs[HD * HD], F[7 * HD];
    const int h = blockIdx.x, oc = blockIdx.y;
    const int tid = threadIdx.x;     // 448 threads
    for (int i = tid; i < HD * HD; i += 448) {
        G[i]  = A[h * HD * HD + i];
        Cs[i] = C[h * HD * HD + i];
    }
    __syncthreads();
    if (tid < HD) {
        #pragma unroll
        for (int e = HD - 2; e >= 0; e--) G[tid * HD + e] += G[tid * HD + e + 1];
    }
    __syncthreads();
    if (tid < 7 * HD) {
        int ol = tid / HD, d = tid % HD;
        float s = 0.f;
        #pragma unroll
        for (int e = 0; e < HD; e++) s += Cs[(oc * 7 + ol) * HD + e] * G[d * HD + e];
        F[ol * HD + d] = s;
    }
    __syncthreads();
    const int i = tid;
    float acc[7] = {0, 0, 0, 0, 0, 0, 0};
    for (int d = 0; d < HD; d++) {
        float b = B[(size_t)(h * HD + d) * DIN + i];
        #pragma unroll
        for (int ol = 0; ol < 7; ol++) acc[ol] += F[ol * HD + d] * b;
    }
    #pragma unroll
    for (int ol = 0; ol < 7; ol++)
        E_g[(size_t)(h * HD + oc * 7 + ol) * DIN + i] = tf32r(acc[ol]);
}

// ---------------- LayerNorm + reshape permutation (tf32-rounded out) -------
__global__ void ln_permute(const float* __restrict__ Y, float* __restrict__ Out,
                           const float* __restrict__ gamma,
                           const float* __restrict__ beta) {
    const int warp = threadIdx.x >> 5, lane = threadIdx.x & 31;
    const int R = blockIdx.x * 8 + warp;
    const int b   = R >> 13;
    const int rem = R & 8191;
    const int h   = rem >> 10;
    const int q   = rem & 1023;

    float v[14];
    #pragma unroll
    for (int j = 0; j < 14; j++) {
        int c = lane + 32 * j;
        int r = c / 56, d = c - r * 56;
        v[j] = Y[(size_t)(b * SEQ + 8 * q + r) * DIN + h * HD + d];
    }
    float s = 0.f;
    #pragma unroll
    for (int j = 0; j < 14; j++) s += v[j];
    #pragma unroll
    for (int o = 16; o > 0; o >>= 1) s += __shfl_xor_sync(0xffffffffu, s, o);
    const float mu = s * (1.f / 448.f);

    float vs = 0.f;
    #pragma unroll
    for (int j = 0; j < 14; j++) { float d2 = v[j] - mu; vs += d2 * d2; }
    #pragma unroll
    for (int o = 16; o > 0; o >>= 1) vs += __shfl_xor_sync(0xffffffffu, vs, o);
    const float rsig = rsqrtf(vs * (1.f / 448.f) + 1e-5f);

    #pragma unroll
    for (int j = 0; j < 14; j++) {
        int c = lane + 32 * j;
        Out[(size_t)R * DIN + c] = tf32r((v[j] - mu) * rsig * gamma[c] + beta[c]);
    }
}

// ---------------------------------------------------------------------------
extern "C" void kernel_launch(void* const* d_in, const int* in_sizes, int n_in,
                              void* d_out, int out_size) {
    const float* x     = (const float*)d_in[0];
    const float* A     = (const float*)d_in[1];
    const float* B     = (const float*)d_in[2];
    const float* C     = (const float*)d_in[3];
    const float* gamma = (const float*)d_in[4];
    const float* beta  = (const float*)d_in[5];
    const float* W     = (const float*)d_in[6];
    const float* bias  = (const float*)d_in[7];
    float* out = (float*)d_out;

    float *E_p, *Wc_p, *Xc_p, *Yg_p, *Yn_p;
    cudaGetSymbolAddress((void**)&E_p,  E_g);
    cudaGetSymbolAddress((void**)&Wc_p, Wc_g);
    cudaGetSymbolAddress((void**)&Xc_p, Xc_g);
    cudaGetSymbolAddress((void**)&Yg_p, Yg_g);
    cudaGetSymbolAddress((void**)&Yn_p, Yn_g);

    cudaFuncSetAttribute(gemm_tf32, cudaFuncAttributeMaxDynamicSharedMemorySize, GSMEM);

    conv_tf32<<<28672, 256>>>((const float4*)x, (float4*)Xc_p, 7340032);
    conv_tf32<<<196,   256>>>((const float4*)W, (float4*)Wc_p, 50176);
    computeE_k<<<dim3(HEADS, 8), DIN>>>(A, B, C);

    dim3 grid(DIN / GBN, TOKENS / GBM);   // (7, 256): N fastest for L2 reuse of A tiles
    gemm_tf32<<<grid, 128, GSMEM>>>(Xc_p, E_p, Yg_p, nullptr);
    ln_permute<<<TOKENS / 8, 256>>>(Yg_p, Yn_p, gamma, beta);
    gemm_tf32<<<grid, 128, GSMEM>>>(Yn_p, Wc_p, out, bias);
}